// round 7
// baseline (speedup 1.0000x reference)
#include <cuda_runtime.h>

// MatchAttention fused forward, fixed shape:
// B=2, H=W=64, N=4096, C=256, heads=8, Ch=32, r=3 -> K=49, scale=1, l1_norm.
#define HH   64
#define WW   64
#define CC   256
#define NHD  8
#define CH   32
#define RR   3
#define KWIN 49
#define NPIX (HH * WW)

// ---- packed f32x2 helpers (sm_10x, PTX-only; ptxas never auto-fuses) -------
__device__ __forceinline__ unsigned long long sub2(unsigned long long a,
                                                   unsigned long long b) {
    unsigned long long r;
    asm("sub.rn.f32x2 %0, %1, %2;" : "=l"(r) : "l"(a), "l"(b));
    return r;
}
__device__ __forceinline__ void fma2(unsigned long long& acc,
                                     unsigned long long v,
                                     unsigned long long w2) {
    asm("fma.rn.f32x2 %0, %1, %2, %0;" : "+l"(acc) : "l"(v), "l"(w2));
}
__device__ __forceinline__ unsigned long long pack2(float a, float b) {
    unsigned long long r;
    asm("mov.b64 %0, {%1, %2};" : "=l"(r) : "f"(a), "f"(b));
    return r;
}
__device__ __forceinline__ void unpack2(unsigned long long p, float& lo, float& hi) {
    asm("mov.b64 {%0, %1}, %2;" : "=f"(lo), "=f"(hi) : "l"(p));
}
__device__ __forceinline__ void mul2(unsigned long long& a, unsigned long long b) {
    asm("mul.rn.f32x2 %0, %0, %1;" : "+l"(a) : "l"(b));
}

// One warp = 4 heads of one pixel (8 lanes/head, 4 channels/lane).
// Slots in 6 groups of 8 + 1 remainder; per group a transposed 3-round
// butterfly leaves lane `lig` holding the FULL L1 distance of slot 8j+lig,
// and only the owner lane runs exp. Streaming softmax with fixed reference
// (sim <= 0 always; d ~ 36+/-5 so exp(-d) is far above fp32 underflow);
// final 1/sum rescale is exactly the reference softmax.
// R7: packed f32x2 for the distance subs and the V accumulation
// (7->5 and 5->4 issued ops per slot respectively).
__global__ __launch_bounds__(256, 5)
void match_attn_kernel(const float* __restrict__ moff,   // [B,N,h,2]
                       const float* __restrict__ qp,     // [B,N,C]
                       const float* __restrict__ kp,     // [B,N,C]
                       const float* __restrict__ vp,     // [B,N,C]
                       float* __restrict__ out,          // [B,N,C]
                       float* __restrict__ attn_out)     // [B,N,h,K]
{
    const int warpGlobal = (blockIdx.x * blockDim.x + threadIdx.x) >> 5;
    const int lane = threadIdx.x & 31;
    const int lig  = lane & 7;    // lane within 8-lane head group
    const int grp  = lane >> 3;   // head-in-half

    const int p = warpGlobal >> 1;               // global pixel (incl batch)
    const int g = (warpGlobal & 1) * 4 + grp;    // head id

    const int n    = p & (NPIX - 1);
    const int base = p - n;                      // b*N
    const int y    = n / WW;
    const int x    = n & (WW - 1);

    // rounded per-head window center (rintf == jnp.round, half-to-even)
    const float2 off2 = *(const float2*)&moff[(size_t)(p * NHD + g) * 2];
    const int cy = y + (int)rintf(off2.x);
    const int cx = x + (int)rintf(off2.y);

    const int chBase = g * CH + lig * 4;

    // clamped row/col element-offsets; chBase folded into the row term
    int pyW[7], pxc[7];
#pragma unroll
    for (int i = 0; i < 7; i++) {
        const int py = min(max(cy + i - RR, 0), HH - 1);
        const int px = min(max(cx + i - RR, 0), WW - 1);
        pyW[i] = (base + py * WW) * CC + chBase;
        pxc[i] = px * CC;
    }

    // q slice kept as two packed f32x2 values
    const ulonglong2 q2 = *(const ulonglong2*)(qp + (size_t)p * CC + chBase);

    const bool b0 = (lig & 1) != 0;
    const bool b1 = (lig & 2) != 0;
    const bool b2 = (lig & 4) != 0;
    const int  gbase = lane & 24;   // first lane of this head group

    float* aout = attn_out + (size_t)(p * NHD + g) * KWIN;

    float s = 0.f;
    unsigned long long acc0 = 0ull, acc1 = 0ull;   // 4 channels as 2 packed pairs

#pragma unroll
    for (int j = 0; j < 6; j++) {
        // ---- shared addresses for this group (k and v gathers) --------------
        int offs[8];
#pragma unroll
        for (int t = 0; t < 8; t++) {
            const int kk = j * 8 + t;
            offs[t] = pyW[kk / 7] + pxc[kk % 7];
        }

        // ---- 8 k-gathers + per-lane partial L1 distances (packed subs) ------
        float pd[8];
#pragma unroll
        for (int t = 0; t < 8; t++) {
            const ulonglong2 k2 = *(const ulonglong2*)(kp + offs[t]);
            float a0, a1, a2, a3;
            unpack2(sub2(q2.x, k2.x), a0, a1);   // q-k for ch 0,1
            unpack2(sub2(q2.y, k2.y), a2, a3);   // q-k for ch 2,3
            // fabs folds into FADD |src| modifiers
            pd[t] = (fabsf(a0) + fabsf(a1)) + (fabsf(a2) + fabsf(a3));
        }

        // ---- transposed butterfly: lane lig ends with full d of slot 8j+lig --
        float r4[4];
#pragma unroll
        for (int t = 0; t < 4; t++) {
            const float keep = b0 ? pd[2 * t + 1] : pd[2 * t];
            const float send = b0 ? pd[2 * t]     : pd[2 * t + 1];
            r4[t] = keep + __shfl_xor_sync(0xffffffffu, send, 1);
        }
        float r2[2];
#pragma unroll
        for (int t = 0; t < 2; t++) {
            const float keep = b1 ? r4[2 * t + 1] : r4[2 * t];
            const float send = b1 ? r4[2 * t]     : r4[2 * t + 1];
            r2[t] = keep + __shfl_xor_sync(0xffffffffu, send, 2);
        }
        const float keep = b2 ? r2[1] : r2[0];
        const float send = b2 ? r2[0] : r2[1];
        const float d = keep + __shfl_xor_sync(0xffffffffu, send, 4);

        const float w = __expf(-d);   // weight of owned slot 8j+lig
        s += w;
        aout[j * 8 + lig] = w;        // stash unnormalized; rescaled in tail

        // ---- v accumulation: broadcast w, packed FMA -------------------------
#pragma unroll
        for (int t = 0; t < 8; t++) {
            const float wt = __shfl_sync(0xffffffffu, w, gbase | t);
            const unsigned long long w2v = pack2(wt, wt);
            const ulonglong2 v2 = *(const ulonglong2*)(vp + offs[t]);
            fma2(acc0, v2.x, w2v);
            fma2(acc1, v2.y, w2v);
        }
    }

    // ---- remainder slot 48 (row 6, col 6) ------------------------------------
    float w48;
    {
        const int off48 = pyW[6] + pxc[6];
        const ulonglong2 k2 = *(const ulonglong2*)(kp + off48);
        float a0, a1, a2, a3;
        unpack2(sub2(q2.x, k2.x), a0, a1);
        unpack2(sub2(q2.y, k2.y), a2, a3);
        float d = (fabsf(a0) + fabsf(a1)) + (fabsf(a2) + fabsf(a3));
        d += __shfl_xor_sync(0xffffffffu, d, 1);
        d += __shfl_xor_sync(0xffffffffu, d, 2);
        d += __shfl_xor_sync(0xffffffffu, d, 4);
        w48 = __expf(-d);                        // full weight on all 8 lanes
        const unsigned long long w2v = pack2(w48, w48);
        const ulonglong2 v2 = *(const ulonglong2*)(vp + off48);
        fma2(acc0, v2.x, w2v);
        fma2(acc1, v2.y, w2v);
    }

    // ---- normalization --------------------------------------------------------
    s += __shfl_xor_sync(0xffffffffu, s, 1);
    s += __shfl_xor_sync(0xffffffffu, s, 2);
    s += __shfl_xor_sync(0xffffffffu, s, 4);
    s += w48;
    const float inv = 1.f / s;

    // rescale stashed weights (same thread wrote them -> ordered, L1-resident)
#pragma unroll
    for (int j = 0; j < 6; j++) aout[j * 8 + lig] *= inv;
    if (lig == 0) aout[48] = w48 * inv;

    const unsigned long long inv2 = pack2(inv, inv);
    mul2(acc0, inv2);
    mul2(acc1, inv2);
    *(ulonglong2*)(out + (size_t)p * CC + chBase) = make_ulonglong2(acc0, acc1);
}

extern "C" void kernel_launch(void* const* d_in, const int* in_sizes, int n_in,
                              void* d_out, int out_size) {
    const float* moff = (const float*)d_in[0];   // [B,N,h,2]
    const float* q    = (const float*)d_in[1];   // [B,N,C]
    const float* k    = (const float*)d_in[2];
    const float* v    = (const float*)d_in[3];

    float* out = (float*)d_out;                  // output [B,N,C] first...
    const int qElems = in_sizes[1];              // B*N*C
    float* attn_out = out + qElems;              // ...then attn_out [B,N,h,K]

    const int items = in_sizes[0] / 2;           // B*N*h
    const int totalWarps = items / 4;            // 4 heads per warp
    const int threads = 256;
    const int blocks = (totalWarps * 32) / threads;   // 2048

    match_attn_kernel<<<blocks, threads>>>(moff, q, k, v, out, attn_out);
}